// round 11
// baseline (speedup 1.0000x reference)
#include <cuda_runtime.h>
#include <math.h>

#define SEQ     2048
#define HIDDEN  2048
#define NHEADS  32
#define NKVH    8
#define HEADDIM 64
#define KVDIM   (NKVH * HEADDIM)   // 512
#define WIN     1024

// Scratch (allocation-free)
__device__ float g_q [SEQ * HIDDEN];
__device__ float g_k [SEQ * KVDIM];
__device__ float g_v [SEQ * KVDIM];
__device__ float g_ao[SEQ * HIDDEN];

// ---------------------------------------------------------------------------
// Naive GEMM (trusted, identical to rounds 4-9)
// ---------------------------------------------------------------------------
__global__ void __launch_bounds__(256) ngemm(const float* __restrict__ A,
                                             const float* __restrict__ B,
                                             float* __restrict__ C,
                                             int src, int dst,
                                             int M, int N, int K)
{
    if (src == 3) A = g_ao;
    if      (dst == 0) C = g_q;
    else if (dst == 1) C = g_k;
    else if (dst == 2) C = g_v;

    int idx = blockIdx.x * 256 + threadIdx.x;
    if (idx >= M * N) return;
    int row = idx / N;
    int col = idx % N;

    const float* a = A + (size_t)row * K;
    const float* b = B + col;
    float acc = 0.0f;
    for (int k = 0; k < K; k++)
        acc = fmaf(a[k], b[(size_t)k * N], acc);
    C[(size_t)row * N + col] = acc;
}

// ---------------------------------------------------------------------------
// RoPE — PROBE A: rotation by NEGATIVE angle, i.e. executed
// _rotate_half(x) = concat([x2, -x1]) instead of concat([-x2, x1]):
//   x1' = x1*cos + x2*sin
//   x2' = x2*cos - x1*sin
// Frequencies unchanged: angle = s * 500000^(-d/32), pairs (d, d+32).
// ---------------------------------------------------------------------------
__global__ void rope_negrot()
{
    const int s = blockIdx.x;
    const int h = blockIdx.y;
    const int d = threadIdx.x;  // 0..31

    double invf = pow(500000.0, -(double)d / 32.0);
    double ang  = (double)s * invf;
    double cd, sd;
    sincos(ang, &cd, &sd);
    float c  = (float)cd;
    float sn = (float)sd;

    float* buf = (h < NHEADS)
        ? (g_q + (size_t)s * HIDDEN + h * HEADDIM)
        : (g_k + (size_t)s * KVDIM + (h - NHEADS) * HEADDIM);

    float x1 = buf[d];
    float x2 = buf[d + 32];
    buf[d]      = x1 * c + x2 * sn;   // <<< PROBE A
    buf[d + 32] = x2 * c - x1 * sn;   // <<< PROBE A
}

// ---------------------------------------------------------------------------
// Attention (trusted round-4 attn3, real scores, nominal 0.125 scale)
// ---------------------------------------------------------------------------
__global__ void __launch_bounds__(64) attn3()
{
    __shared__ float sc [WIN];
    __shared__ float qsh[64];
    __shared__ float red[64];

    const int row  = blockIdx.x;
    const int h    = blockIdx.y;
    const int kvh  = h >> 2;
    const int tid  = threadIdx.x;   // 0..63
    const int lane = tid & 31;
    const int warp = tid >> 5;

    qsh[tid] = g_q[(size_t)row * HIDDEN + h * HEADDIM + tid] * 0.125f;
    __syncthreads();

    int cBeg = row - (WIN - 1);
    if (cBeg < 0) cBeg = 0;
    const int n = row - cBeg + 1;

    const float q0 = qsh[lane];
    const float q1 = qsh[lane + 32];
    for (int j = warp; j < n; j += 2) {
        const float* kr = g_k + (size_t)(cBeg + j) * KVDIM + kvh * HEADDIM;
        float p = q0 * kr[lane] + q1 * kr[lane + 32];
        p += __shfl_xor_sync(0xffffffffu, p, 16);
        p += __shfl_xor_sync(0xffffffffu, p, 8);
        p += __shfl_xor_sync(0xffffffffu, p, 4);
        p += __shfl_xor_sync(0xffffffffu, p, 2);
        p += __shfl_xor_sync(0xffffffffu, p, 1);
        if (lane == 0) sc[j] = p;
    }
    __syncthreads();

    // exact two-pass softmax
    float mx = -1e30f;
    for (int j = tid; j < n; j += 64) mx = fmaxf(mx, sc[j]);
    red[tid] = mx;
    __syncthreads();
    if (tid == 0) {
        float m = red[0];
        for (int i = 1; i < 64; i++) m = fmaxf(m, red[i]);
        red[0] = m;
    }
    __syncthreads();
    const float m = red[0];
    __syncthreads();

    float sum = 0.0f;
    for (int j = tid; j < n; j += 64) {
        float p = expf(sc[j] - m);
        sc[j] = p;
        sum += p;
    }
    red[tid] = sum;
    __syncthreads();
    if (tid == 0) {
        float l = 0.0f;
        for (int i = 0; i < 64; i++) l += red[i];
        red[0] = l;
    }
    __syncthreads();
    const float linv = 1.0f / red[0];

    float o = 0.0f;
    for (int j = 0; j < n; j++)
        o = fmaf(sc[j], g_v[(size_t)(cBeg + j) * KVDIM + kvh * HEADDIM + tid], o);

    g_ao[(size_t)row * HIDDEN + h * HEADDIM + tid] = o * linv;
}

// ---------------------------------------------------------------------------
extern "C" void kernel_launch(void* const* d_in, const int* in_sizes, int n_in,
                              void* d_out, int out_size)
{
    const float* X  = (const float*)d_in[0];
    const float* Wq = (const float*)d_in[1];
    const float* Wk = (const float*)d_in[2];
    const float* Wv = (const float*)d_in[3];
    const float* Wo = (const float*)d_in[4];
    float* out = (float*)d_out;

    ngemm<<<(SEQ * HIDDEN) / 256, 256>>>(X, Wq, nullptr, 0, 0, SEQ, HIDDEN, HIDDEN);
    ngemm<<<(SEQ * KVDIM ) / 256, 256>>>(X, Wk, nullptr, 0, 1, SEQ, KVDIM,  HIDDEN);
    ngemm<<<(SEQ * KVDIM ) / 256, 256>>>(X, Wv, nullptr, 0, 2, SEQ, KVDIM,  HIDDEN);

    rope_negrot<<<dim3(SEQ, NHEADS + NKVH), 32>>>();

    attn3<<<dim3(SEQ, NHEADS), 64>>>();

    ngemm<<<(SEQ * HIDDEN) / 256, 256>>>(nullptr, Wo, out, 3, 9, SEQ, HIDDEN, HIDDEN);
}